// round 2
// baseline (speedup 1.0000x reference)
#include <cuda_runtime.h>
#include <cstddef>

#define NN      100000
#define EE      1200000
#define NFEAT_K 128
#define NHID    64
#define NCLASS  16

// Scratch: ~25.6MB each. __device__ globals (no runtime allocation allowed).
__device__ float g_h0 [(size_t)NN * NHID];   // h = x@fc0_w + fc0_b (pre-ReLU)
__device__ float g_xw [(size_t)NN * NHID];   // relu(prev) @ conv_w[i]
__device__ float g_bufA[(size_t)NN * NHID];  // layer outputs (ping)
__device__ float g_bufB[(size_t)NN * NHID];  // layer outputs (pong)

// ---------------------------------------------------------------------------
// Row-sliced GEMM: out[r,:] = act(in[r,:]) @ W[K,N] + b
// S threads cooperate on one row, each producing N/S outputs.
// Cuts accumulator registers S-fold vs one-thread-per-row -> high occupancy.
// W staged in smem; 4-thread groups read the same x float4 (L1 broadcast).
// ---------------------------------------------------------------------------
template<int K, int N, int S, bool RELU_IN>
__global__ __launch_bounds__(256)
void gemm_bias_kernel(const float* __restrict__ in,
                      const float* __restrict__ W,
                      const float* __restrict__ b,
                      float* __restrict__ out)
{
    constexpr int NS  = N / S;    // outputs per thread
    constexpr int NS4 = NS / 4;
    constexpr int RPB = 256 / S;  // rows per block

    __shared__ float Ws[K * N];
    __shared__ float bs[N];
    for (int i = threadIdx.x; i < K * N; i += 256) Ws[i] = W[i];
    for (int i = threadIdx.x; i < N;     i += 256) bs[i] = b[i];
    __syncthreads();

    const int slice = threadIdx.x % S;
    const int row   = blockIdx.x * RPB + threadIdx.x / S;
    if (row >= NN) return;

    float4 acc[NS4];
    const float4* b4 = (const float4*)(bs + slice * NS);
#pragma unroll
    for (int n = 0; n < NS4; n++) acc[n] = b4[n];

    const float4* inr = (const float4*)(in + (size_t)row * K);
#pragma unroll 4
    for (int k4 = 0; k4 < K / 4; k4++) {
        float4 xv = __ldg(inr + k4);
        float xs[4];
        if (RELU_IN) {
            xs[0] = fmaxf(xv.x, 0.f); xs[1] = fmaxf(xv.y, 0.f);
            xs[2] = fmaxf(xv.z, 0.f); xs[3] = fmaxf(xv.w, 0.f);
        } else {
            xs[0] = xv.x; xs[1] = xv.y; xs[2] = xv.z; xs[3] = xv.w;
        }
#pragma unroll
        for (int kk = 0; kk < 4; kk++) {
            const float4* w4 = (const float4*)(Ws + (size_t)(k4 * 4 + kk) * N + slice * NS);
#pragma unroll
            for (int n = 0; n < NS4; n++) {
                float4 w = w4[n];
                acc[n].x = fmaf(xs[kk], w.x, acc[n].x);
                acc[n].y = fmaf(xs[kk], w.y, acc[n].y);
                acc[n].z = fmaf(xs[kk], w.z, acc[n].z);
                acc[n].w = fmaf(xs[kk], w.w, acc[n].w);
            }
        }
    }

    float4* o = (float4*)(out + (size_t)row * N + slice * NS);
#pragma unroll
    for (int n = 0; n < NS4; n++) o[n] = acc[n];
}

// ---------------------------------------------------------------------------
// Per-layer dense part, fused, S=4 slicing:
//   xw[r,:]      = relu(in[r,:]) @ W          (SpMM operand)
//   outinit[r,:] = 0.1*h0[r,:] + cb[:]        (SpMM accumulator pre-init)
// (theta cancels in the reference: out = support + b)
// ---------------------------------------------------------------------------
__global__ __launch_bounds__(256)
void conv_gemm_kernel(const float* __restrict__ in,
                      const float* __restrict__ W,
                      const float* __restrict__ h0,
                      const float* __restrict__ cb,
                      float* __restrict__ xw,
                      float* __restrict__ outinit)
{
    constexpr int S   = 4;
    constexpr int NS  = NHID / S;   // 16
    constexpr int NS4 = NS / 4;     // 4
    constexpr int RPB = 256 / S;    // 64

    __shared__ float Ws[NHID * NHID];
    __shared__ float cbs[NHID];
    for (int i = threadIdx.x; i < NHID * NHID; i += 256) Ws[i] = W[i];
    if (threadIdx.x < NHID) cbs[threadIdx.x] = cb[threadIdx.x];
    __syncthreads();

    const int slice = threadIdx.x % S;
    const int row   = blockIdx.x * RPB + threadIdx.x / S;
    if (row >= NN) return;

    float4 acc[NS4];
#pragma unroll
    for (int n = 0; n < NS4; n++) acc[n] = make_float4(0.f, 0.f, 0.f, 0.f);

    const float4* inr = (const float4*)(in + (size_t)row * NHID);
#pragma unroll 4
    for (int k4 = 0; k4 < NHID / 4; k4++) {
        float4 xv = __ldg(inr + k4);
        float xs[4] = { fmaxf(xv.x, 0.f), fmaxf(xv.y, 0.f),
                        fmaxf(xv.z, 0.f), fmaxf(xv.w, 0.f) };
#pragma unroll
        for (int kk = 0; kk < 4; kk++) {
            const float4* w4 = (const float4*)(Ws + (size_t)(k4 * 4 + kk) * NHID + slice * NS);
#pragma unroll
            for (int n = 0; n < NS4; n++) {
                float4 w = w4[n];
                acc[n].x = fmaf(xs[kk], w.x, acc[n].x);
                acc[n].y = fmaf(xs[kk], w.y, acc[n].y);
                acc[n].z = fmaf(xs[kk], w.z, acc[n].z);
                acc[n].w = fmaf(xs[kk], w.w, acc[n].w);
            }
        }
    }

    float4*       xo  = (float4*)(xw + (size_t)row * NHID + slice * NS);
    const float4* h0r = (const float4*)(h0 + (size_t)row * NHID + slice * NS);
    float4*       oi  = (float4*)(outinit + (size_t)row * NHID + slice * NS);
    const float4* cb4 = (const float4*)(cbs + slice * NS);
#pragma unroll
    for (int n = 0; n < NS4; n++) {
        xo[n] = acc[n];
        float4 h = __ldg(h0r + n);
        float4 c = cb4[n];
        oi[n] = make_float4(fmaf(0.1f, h.x, c.x), fmaf(0.1f, h.y, c.y),
                            fmaf(0.1f, h.z, c.z), fmaf(0.1f, h.w, c.w));
    }
}

// ---------------------------------------------------------------------------
// SpMM scatter: out[rows[e],:] += 0.9 * vals[e] * xw[cols[e],:]
// 16 threads per edge, each handles one float4 (coalesced 256B gather),
// vectorized float4 atomicAdd (sm_90+) -> 1 L2 red-op per 16 bytes.
// ---------------------------------------------------------------------------
__global__ __launch_bounds__(256)
void spmm_scatter_kernel(const int*   __restrict__ rows,
                         const int*   __restrict__ cols,
                         const float* __restrict__ vals,
                         const float* __restrict__ xw,
                         float*       __restrict__ out)
{
    long long tid = (long long)blockIdx.x * 256 + threadIdx.x;
    int e = (int)(tid >> 4);
    if (e >= EE) return;
    int j = (int)(tid & 15);

    int   c = __ldg(cols + e);
    int   r = __ldg(rows + e);
    float v = 0.9f * __ldg(vals + e);

    float4 xv = __ldg((const float4*)(xw + (size_t)c * NHID) + j);
    float4 m  = make_float4(v * xv.x, v * xv.y, v * xv.z, v * xv.w);

    float4* dst = (float4*)(out + (size_t)r * NHID) + j;
    atomicAdd(dst, m);   // vector red.global to L2
}

// ---------------------------------------------------------------------------
extern "C" void kernel_launch(void* const* d_in, const int* in_sizes, int n_in,
                              void* d_out, int out_size)
{
    const float* x        = (const float*)d_in[0];
    const int*   adj_rows = (const int*)  d_in[1];
    const int*   adj_cols = (const int*)  d_in[2];
    const float* adj_vals = (const float*)d_in[3];
    const float* fc0_w    = (const float*)d_in[4];
    const float* fc0_b    = (const float*)d_in[5];
    const float* conv_w   = (const float*)d_in[6];
    const float* conv_b   = (const float*)d_in[7];
    const float* fc1_w    = (const float*)d_in[8];
    const float* fc1_b    = (const float*)d_in[9];
    float* out = (float*)d_out;

    float *h0p, *xwp, *ap, *bp;
    cudaGetSymbolAddress((void**)&h0p, g_h0);
    cudaGetSymbolAddress((void**)&xwp, g_xw);
    cudaGetSymbolAddress((void**)&ap,  g_bufA);
    cudaGetSymbolAddress((void**)&bp,  g_bufB);

    const int EDGE_BLOCKS = (int)(((long long)EE * 16 + 255) / 256);

    // fc0: h0 = x @ fc0_w + fc0_b  (S=4 slicing, 64 rows/block)
    gemm_bias_kernel<NFEAT_K, NHID, 4, false><<<(NN + 63) / 64, 256>>>(x, fc0_w, fc0_b, h0p);

    // 4 GCNII layers; ping-pong bufA/bufB, layer-0 input is h0.
    float* prev = h0p;
    float* bufs[2] = { ap, bp };
    for (int i = 0; i < 4; i++) {
        float* next = bufs[i & 1];
        conv_gemm_kernel<<<(NN + 63) / 64, 256>>>(
            prev, conv_w + (size_t)i * NHID * NHID, h0p, conv_b + (size_t)i * NHID,
            xwp, next);
        spmm_scatter_kernel<<<EDGE_BLOCKS, 256>>>(adj_rows, adj_cols, adj_vals, xwp, next);
        prev = next;
    }

    // fc1: out = relu(prev) @ fc1_w + fc1_b  (S=1: only 4 accumulators)
    gemm_bias_kernel<NHID, NCLASS, 1, true><<<(NN + 255) / 256, 256>>>(prev, fc1_w, fc1_b, out);
}

// round 3
// speedup vs baseline: 1.8496x; 1.8496x over previous
#include <cuda_runtime.h>
#include <cstddef>

#define NN      100000
#define EE      1200000
#define NFEAT_K 128
#define NHID    64
#define NCLASS  16

// Scratch: ~25.6MB each. __device__ globals (no runtime allocation allowed).
__device__ float g_h0 [(size_t)NN * NHID];   // h = x@fc0_w + fc0_b (pre-ReLU)
__device__ float g_xw [(size_t)NN * NHID];   // relu(prev) @ conv_w[i]
__device__ float g_bufA[(size_t)NN * NHID];  // layer outputs (ping)
__device__ float g_bufB[(size_t)NN * NHID];  // layer outputs (pong)

// ---------------------------------------------------------------------------
// Register-tiled GEMM: out0[r,:] = act(in[r,:]) @ W[K,64] (+ b)
// Block tile: 128 rows x 64 cols x BK=64. 256 threads, thread tile 8x4.
// W tile reused across 128 rows from smem -> LDS traffic drops ~16x vs
// per-row designs; kernel becomes FFMA-issue bound (the true floor).
// Optional fused epilogue writes out1[r,:] = 0.1*h0[r,:] + cb[:] (SpMM init).
// ---------------------------------------------------------------------------
template<int K, bool RELU_IN, bool ADD_BIAS, bool FUSE_EPI>
__global__ __launch_bounds__(256)
void tile_gemm(const float* __restrict__ in, const float* __restrict__ W,
               const float* __restrict__ b,
               const float* __restrict__ h0, const float* __restrict__ cb,
               float* __restrict__ out0, float* __restrict__ out1)
{
    constexpr int BM = 128, BN = 64, BK = 64;
    __shared__ float xs[BM][BK];   // x tile, natural layout (broadcast scalar reads)
    __shared__ float ws[BK][BN];   // W tile

    const int row0 = blockIdx.x * BM;
    const int t  = threadIdx.x;
    const int ng = t & 15;         // column group: 16 groups of 4 cols
    const int mg = t >> 4;         // row group:    16 groups of 8 rows
    const int n_base = ng * 4;
    const int m_base = mg * 8;

    float4 acc[8];
#pragma unroll
    for (int r = 0; r < 8; r++) acc[r] = make_float4(0.f, 0.f, 0.f, 0.f);

    for (int kt = 0; kt < K; kt += BK) {
        // Stage W chunk [BK][BN] (contiguous in gmem since W is [K][N] row-major)
        {
            const float4* Wg  = (const float4*)(W + (size_t)kt * BN);
            float4*       wsd = (float4*)ws;
            for (int i = t; i < BK * BN / 4; i += 256) wsd[i] = __ldg(Wg + i);
        }
        // Stage x chunk [BM][BK], coalesced float4, ReLU applied on load
        for (int i = t; i < BM * BK / 4; i += 256) {
            int r  = i >> 4;       // BK/4 == 16
            int k4 = i & 15;
            int row = row0 + r;
            float4 v = make_float4(0.f, 0.f, 0.f, 0.f);
            if (row < NN) v = __ldg((const float4*)(in + (size_t)row * K + kt) + k4);
            if (RELU_IN) {
                v.x = fmaxf(v.x, 0.f); v.y = fmaxf(v.y, 0.f);
                v.z = fmaxf(v.z, 0.f); v.w = fmaxf(v.w, 0.f);
            }
            *((float4*)&xs[r][k4 * 4]) = v;
        }
        __syncthreads();

#pragma unroll 8
        for (int k = 0; k < BK; k++) {
            float4 w = *(const float4*)&ws[k][n_base];
#pragma unroll
            for (int r = 0; r < 8; r++) {
                float xv = xs[m_base + r][k];
                acc[r].x = fmaf(xv, w.x, acc[r].x);
                acc[r].y = fmaf(xv, w.y, acc[r].y);
                acc[r].z = fmaf(xv, w.z, acc[r].z);
                acc[r].w = fmaf(xv, w.w, acc[r].w);
            }
        }
        __syncthreads();
    }

    float4 bias = make_float4(0.f, 0.f, 0.f, 0.f);
    if (ADD_BIAS) bias = __ldg((const float4*)(b + n_base));
    float4 cbv = make_float4(0.f, 0.f, 0.f, 0.f);
    if (FUSE_EPI) cbv = __ldg((const float4*)(cb + n_base));

#pragma unroll
    for (int r = 0; r < 8; r++) {
        int row = row0 + m_base + r;
        if (row >= NN) break;
        float4 o = acc[r];
        if (ADD_BIAS) { o.x += bias.x; o.y += bias.y; o.z += bias.z; o.w += bias.w; }
        *((float4*)(out0 + (size_t)row * BN + n_base)) = o;
        if (FUSE_EPI) {
            float4 h = __ldg((const float4*)(h0 + (size_t)row * BN + n_base));
            float4 oi = make_float4(fmaf(0.1f, h.x, cbv.x), fmaf(0.1f, h.y, cbv.y),
                                    fmaf(0.1f, h.z, cbv.z), fmaf(0.1f, h.w, cbv.w));
            *((float4*)(out1 + (size_t)row * BN + n_base)) = oi;
        }
    }
}

// ---------------------------------------------------------------------------
// fc1: out[r,:] = relu(in[r,:]) @ W[64,16] + b. One thread per row (4 accum
// float4 -> low regs, fine). Tiny kernel, not on the critical path.
// ---------------------------------------------------------------------------
__global__ __launch_bounds__(256)
void fc1_kernel(const float* __restrict__ in, const float* __restrict__ W,
                const float* __restrict__ b, float* __restrict__ out)
{
    __shared__ float Ws[NHID * NCLASS];
    __shared__ float bs[NCLASS];
    for (int i = threadIdx.x; i < NHID * NCLASS; i += 256) Ws[i] = W[i];
    if (threadIdx.x < NCLASS) bs[threadIdx.x] = b[threadIdx.x];
    __syncthreads();

    int row = blockIdx.x * 256 + threadIdx.x;
    if (row >= NN) return;

    float4 acc[4];
    const float4* b4 = (const float4*)bs;
#pragma unroll
    for (int n = 0; n < 4; n++) acc[n] = b4[n];

    const float4* inr = (const float4*)(in + (size_t)row * NHID);
#pragma unroll 4
    for (int k4 = 0; k4 < NHID / 4; k4++) {
        float4 xv = __ldg(inr + k4);
        float xs[4] = { fmaxf(xv.x, 0.f), fmaxf(xv.y, 0.f),
                        fmaxf(xv.z, 0.f), fmaxf(xv.w, 0.f) };
#pragma unroll
        for (int kk = 0; kk < 4; kk++) {
            const float4* w4 = (const float4*)(Ws + (size_t)(k4 * 4 + kk) * NCLASS);
#pragma unroll
            for (int n = 0; n < 4; n++) {
                float4 w = w4[n];
                acc[n].x = fmaf(xs[kk], w.x, acc[n].x);
                acc[n].y = fmaf(xs[kk], w.y, acc[n].y);
                acc[n].z = fmaf(xs[kk], w.z, acc[n].z);
                acc[n].w = fmaf(xs[kk], w.w, acc[n].w);
            }
        }
    }

    float4* o = (float4*)(out + (size_t)row * NCLASS);
#pragma unroll
    for (int n = 0; n < 4; n++) o[n] = acc[n];
}

// ---------------------------------------------------------------------------
// SpMM scatter: out[rows[e],:] += 0.9 * vals[e] * xw[cols[e],:]
// 16 threads per edge, each handles one float4 (coalesced 256B gather),
// vectorized float4 atomicAdd (sm_90+) -> 1 L2 red-op per 16 bytes.
// ---------------------------------------------------------------------------
__global__ __launch_bounds__(256)
void spmm_scatter_kernel(const int*   __restrict__ rows,
                         const int*   __restrict__ cols,
                         const float* __restrict__ vals,
                         const float* __restrict__ xw,
                         float*       __restrict__ out)
{
    long long tid = (long long)blockIdx.x * 256 + threadIdx.x;
    int e = (int)(tid >> 4);
    if (e >= EE) return;
    int j = (int)(tid & 15);

    int   c = __ldg(cols + e);
    int   r = __ldg(rows + e);
    float v = 0.9f * __ldg(vals + e);

    float4 xv = __ldg((const float4*)(xw + (size_t)c * NHID) + j);
    float4 m  = make_float4(v * xv.x, v * xv.y, v * xv.z, v * xv.w);

    float4* dst = (float4*)(out + (size_t)r * NHID) + j;
    atomicAdd(dst, m);   // vector red.global to L2
}

// ---------------------------------------------------------------------------
extern "C" void kernel_launch(void* const* d_in, const int* in_sizes, int n_in,
                              void* d_out, int out_size)
{
    const float* x        = (const float*)d_in[0];
    const int*   adj_rows = (const int*)  d_in[1];
    const int*   adj_cols = (const int*)  d_in[2];
    const float* adj_vals = (const float*)d_in[3];
    const float* fc0_w    = (const float*)d_in[4];
    const float* fc0_b    = (const float*)d_in[5];
    const float* conv_w   = (const float*)d_in[6];
    const float* conv_b   = (const float*)d_in[7];
    const float* fc1_w    = (const float*)d_in[8];
    const float* fc1_b    = (const float*)d_in[9];
    float* out = (float*)d_out;

    float *h0p, *xwp, *ap, *bp;
    cudaGetSymbolAddress((void**)&h0p, g_h0);
    cudaGetSymbolAddress((void**)&xwp, g_xw);
    cudaGetSymbolAddress((void**)&ap,  g_bufA);
    cudaGetSymbolAddress((void**)&bp,  g_bufB);

    const int GEMM_BLOCKS = (NN + 127) / 128;   // 782
    const int EDGE_BLOCKS = (int)(((long long)EE * 16 + 255) / 256);

    // fc0: h0 = x @ fc0_w + fc0_b   (pre-ReLU; ReLU applied at consumers)
    tile_gemm<NFEAT_K, false, true, false><<<GEMM_BLOCKS, 256>>>(
        x, fc0_w, fc0_b, nullptr, nullptr, h0p, nullptr);

    // 4 GCNII layers; ping-pong bufA/bufB, layer-0 input is h0.
    // Per layer: xw = relu(prev) @ conv_w[i];  next = 0.1*h0 + cb  (fused),
    // then SpMM scatters 0.9*A*xw into next. (theta cancels: out = support+b)
    float* prev = h0p;
    float* bufs[2] = { ap, bp };
    for (int i = 0; i < 4; i++) {
        float* next = bufs[i & 1];
        tile_gemm<NHID, true, false, true><<<GEMM_BLOCKS, 256>>>(
            prev, conv_w + (size_t)i * NHID * NHID, nullptr,
            h0p, conv_b + (size_t)i * NHID, xwp, next);
        spmm_scatter_kernel<<<EDGE_BLOCKS, 256>>>(adj_rows, adj_cols, adj_vals, xwp, next);
        prev = next;
    }

    // fc1: out = relu(prev) @ fc1_w + fc1_b
    fc1_kernel<<<(NN + 255) / 256, 256>>>(prev, fc1_w, fc1_b, out);
}

// round 4
// speedup vs baseline: 2.6437x; 1.4293x over previous
#include <cuda_runtime.h>
#include <cstddef>

#define NN      100000
#define EE      1200000
#define NFEAT_K 128
#define NHID    64
#define NCLASS  16

// ---- scratch (__device__ globals; no runtime allocation allowed) ----------
__device__ float g_h0 [(size_t)NN * NHID];    // h = x@fc0_w + fc0_b (pre-ReLU)
__device__ float g_xw [(size_t)NN * NHID];    // relu(prev) @ conv_w[i]
__device__ float g_bufA[(size_t)NN * NHID];   // layer outputs (ping)
__device__ float g_bufB[(size_t)NN * NHID];   // layer outputs (pong)
// CSR (built once per launch; adjacency is identical across the 4 layers)
__device__ int   g_cnt   [NN];
__device__ int   g_excl  [NN];
__device__ int   g_bsum  [256];
__device__ int   g_rptr  [NN + 1];
__device__ int   g_cursor[NN];
__device__ int2  g_ev    [EE];                // (col, __float_as_int(0.9*val))

// ---------------------------------------------------------------------------
// Register-tiled GEMM: out[r,:] = act(in[r,:]) @ W[K,64] (+ b)
// Block tile 128x64xBK=64, 256 threads, thread tile 8 rows x 4 cols.
// x is read as float4 along k (4 k-steps per LDS) -> per warp-4k only ~12 LDS
// vs 128 FFMA/thread: FFMA-issue bound.
// ---------------------------------------------------------------------------
template<int K, bool RELU_IN, bool ADD_BIAS>
__global__ __launch_bounds__(256)
void tile_gemm(const float* __restrict__ in, const float* __restrict__ W,
               const float* __restrict__ b, float* __restrict__ out)
{
    constexpr int BM = 128, BN = 64, BK = 64;
    __shared__ float4 xs4[BM][BK / 4];   // 32KB
    __shared__ float4 ws4[BK][BN / 4];   // 16KB

    const int t    = threadIdx.x;
    const int ng   = t & 15;             // column group (4 cols)
    const int mg   = t >> 4;             // row group (8 rows)
    const int row0 = blockIdx.x * BM;

    float4 acc[8];
#pragma unroll
    for (int r = 0; r < 8; r++) acc[r] = make_float4(0.f, 0.f, 0.f, 0.f);

    for (int kt = 0; kt < K; kt += BK) {
        // Stage W chunk [BK][BN]: contiguous float4s (W row-major [K][64])
        {
            const float4* Wg = (const float4*)(W + (size_t)kt * BN);
#pragma unroll
            for (int i = t; i < BK * BN / 4; i += 256)
                ws4[i >> 4][i & 15] = __ldg(Wg + i);
        }
        // Stage x chunk [BM][BK]: coalesced float4, ReLU applied on load
#pragma unroll
        for (int i = t; i < BM * BK / 4; i += 256) {
            int r  = i >> 4;
            int k4 = i & 15;
            int row = row0 + r;
            float4 v = make_float4(0.f, 0.f, 0.f, 0.f);
            if (row < NN) v = __ldg((const float4*)(in + (size_t)row * K + kt) + k4);
            if (RELU_IN) {
                v.x = fmaxf(v.x, 0.f); v.y = fmaxf(v.y, 0.f);
                v.z = fmaxf(v.z, 0.f); v.w = fmaxf(v.w, 0.f);
            }
            xs4[r][k4] = v;
        }
        __syncthreads();

#pragma unroll 4
        for (int k4 = 0; k4 < BK / 4; k4++) {
            float4 w0 = ws4[k4 * 4 + 0][ng];
            float4 w1 = ws4[k4 * 4 + 1][ng];
            float4 w2 = ws4[k4 * 4 + 2][ng];
            float4 w3 = ws4[k4 * 4 + 3][ng];
#pragma unroll
            for (int r = 0; r < 8; r++) {
                float4 xv = xs4[mg * 8 + r][k4];
                acc[r].x = fmaf(xv.x, w0.x, acc[r].x);
                acc[r].y = fmaf(xv.x, w0.y, acc[r].y);
                acc[r].z = fmaf(xv.x, w0.z, acc[r].z);
                acc[r].w = fmaf(xv.x, w0.w, acc[r].w);
                acc[r].x = fmaf(xv.y, w1.x, acc[r].x);
                acc[r].y = fmaf(xv.y, w1.y, acc[r].y);
                acc[r].z = fmaf(xv.y, w1.z, acc[r].z);
                acc[r].w = fmaf(xv.y, w1.w, acc[r].w);
                acc[r].x = fmaf(xv.z, w2.x, acc[r].x);
                acc[r].y = fmaf(xv.z, w2.y, acc[r].y);
                acc[r].z = fmaf(xv.z, w2.z, acc[r].z);
                acc[r].w = fmaf(xv.z, w2.w, acc[r].w);
                acc[r].x = fmaf(xv.w, w3.x, acc[r].x);
                acc[r].y = fmaf(xv.w, w3.y, acc[r].y);
                acc[r].z = fmaf(xv.w, w3.z, acc[r].z);
                acc[r].w = fmaf(xv.w, w3.w, acc[r].w);
            }
        }
        __syncthreads();
    }

    float4 bias = make_float4(0.f, 0.f, 0.f, 0.f);
    if (ADD_BIAS) bias = __ldg((const float4*)(b + ng * 4));
#pragma unroll
    for (int r = 0; r < 8; r++) {
        int row = row0 + mg * 8 + r;
        if (row >= NN) break;
        float4 o = acc[r];
        if (ADD_BIAS) { o.x += bias.x; o.y += bias.y; o.z += bias.z; o.w += bias.w; }
        *((float4*)(out + (size_t)row * BN + ng * 4)) = o;
    }
}

// ---------------------------------------------------------------------------
// CSR build kernels (adjacency fixed across layers -> build once per launch)
// ---------------------------------------------------------------------------
__global__ void k_zero(int* __restrict__ p, int n)
{
    int i = blockIdx.x * 256 + threadIdx.x;
    if (i < n) p[i] = 0;
}

__global__ void k_hist(const int* __restrict__ rows, int* __restrict__ cnt)
{
    int e = blockIdx.x * 256 + threadIdx.x;
    if (e < EE) atomicAdd(cnt + __ldg(rows + e), 1);
}

// block-wide exclusive scan helper (512 threads)
__device__ __forceinline__ int block_scan_excl_512(int v, int* total)
{
    int lane = threadIdx.x & 31, warp = threadIdx.x >> 5;
    int x = v;
#pragma unroll
    for (int d = 1; d < 32; d <<= 1) {
        int y = __shfl_up_sync(0xffffffffu, x, d);
        if (lane >= d) x += y;
    }
    __shared__ int wsum[16];
    if (lane == 31) wsum[warp] = x;
    __syncthreads();
    if (warp == 0) {
        int y = (lane < 16) ? wsum[lane] : 0;
#pragma unroll
        for (int d = 1; d < 16; d <<= 1) {
            int z = __shfl_up_sync(0xffffffffu, y, d);
            if (lane >= d) y += z;
        }
        if (lane < 16) wsum[lane] = y;
    }
    __syncthreads();
    int off = (warp > 0) ? wsum[warp - 1] : 0;
    if (total) *total = wsum[15];
    return x + off - v;   // exclusive
}

__global__ __launch_bounds__(512)
void k_scan1(const int* __restrict__ cnt, int* __restrict__ excl, int* __restrict__ bsum)
{
    int i = blockIdx.x * 512 + threadIdx.x;
    int v = (i < NN) ? cnt[i] : 0;
    int total;
    int ex = block_scan_excl_512(v, &total);
    if (i < NN) excl[i] = ex;
    if (threadIdx.x == 0) bsum[blockIdx.x] = total;
}

__global__ __launch_bounds__(512)
void k_scan2(int* __restrict__ bsum, int nblk)   // single block: in-place exclusive scan
{
    int v = (threadIdx.x < nblk) ? bsum[threadIdx.x] : 0;
    int ex = block_scan_excl_512(v, nullptr);
    if (threadIdx.x < nblk) bsum[threadIdx.x] = ex;
}

__global__ __launch_bounds__(512)
void k_finish(const int* __restrict__ excl, const int* __restrict__ bsum,
              int* __restrict__ rptr, int* __restrict__ cursor)
{
    int i = blockIdx.x * 512 + threadIdx.x;
    if (i < NN) {
        int v = excl[i] + bsum[blockIdx.x];
        rptr[i] = v;
        cursor[i] = v;
    }
    if (i == 0) rptr[NN] = EE;
}

__global__ void k_fill(const int* __restrict__ rows, const int* __restrict__ cols,
                       const float* __restrict__ vals,
                       int* __restrict__ cursor, int2* __restrict__ ev)
{
    int e = blockIdx.x * 256 + threadIdx.x;
    if (e >= EE) return;
    int r = __ldg(rows + e);
    int p = atomicAdd(cursor + r, 1);
    ev[p] = make_int2(__ldg(cols + e), __float_as_int(0.9f * __ldg(vals + e)));
}

// ---------------------------------------------------------------------------
// SpMM pull (CSR by destination) with fused GCNII epilogue:
//   out[r,:] = 0.1*h0[r,:] + cb[:] + sum_e 0.9*val_e * xw[col_e,:]
// One warp per row; lane owns a float2 of the 64-wide feature. No atomics.
// ---------------------------------------------------------------------------
__global__ __launch_bounds__(256)
void spmm_pull(const int* __restrict__ rptr, const int2* __restrict__ ev,
               const float* __restrict__ xw, const float* __restrict__ h0,
               const float* __restrict__ cb, float* __restrict__ out)
{
    int warp = (blockIdx.x * 256 + threadIdx.x) >> 5;   // row id
    int lane = threadIdx.x & 31;
    if (warp >= NN) return;
    int r = warp;

    int start = __ldg(rptr + r);
    int end   = __ldg(rptr + r + 1);

    float2 h  = __ldg((const float2*)(h0 + (size_t)r * NHID) + lane);
    float2 c  = __ldg((const float2*)cb + lane);
    float2 acc = make_float2(fmaf(0.1f, h.x, c.x), fmaf(0.1f, h.y, c.y));

    int e = start;
    int2 nxt = (e < end) ? __ldg(ev + e) : make_int2(0, 0);
    while (e < end) {
        int2 cur = nxt;
        if (e + 1 < end) nxt = __ldg(ev + e + 1);
        float v = __int_as_float(cur.y);
        float2 xv = __ldg((const float2*)(xw + (size_t)cur.x * NHID) + lane);
        acc.x = fmaf(v, xv.x, acc.x);
        acc.y = fmaf(v, xv.y, acc.y);
        e++;
    }

    *((float2*)(out + (size_t)r * NHID) + lane) = acc;
}

// ---------------------------------------------------------------------------
// fc1: out[r,:] = relu(in[r,:]) @ W[64,16] + b. One thread per row.
// ---------------------------------------------------------------------------
__global__ __launch_bounds__(256)
void fc1_kernel(const float* __restrict__ in, const float* __restrict__ W,
                const float* __restrict__ b, float* __restrict__ out)
{
    __shared__ float Ws[NHID * NCLASS];
    __shared__ float bs[NCLASS];
    for (int i = threadIdx.x; i < NHID * NCLASS; i += 256) Ws[i] = W[i];
    if (threadIdx.x < NCLASS) bs[threadIdx.x] = b[threadIdx.x];
    __syncthreads();

    int row = blockIdx.x * 256 + threadIdx.x;
    if (row >= NN) return;

    float4 acc[4];
    const float4* b4 = (const float4*)bs;
#pragma unroll
    for (int n = 0; n < 4; n++) acc[n] = b4[n];

    const float4* inr = (const float4*)(in + (size_t)row * NHID);
#pragma unroll 4
    for (int k4 = 0; k4 < NHID / 4; k4++) {
        float4 xv = __ldg(inr + k4);
        float xs[4] = { fmaxf(xv.x, 0.f), fmaxf(xv.y, 0.f),
                        fmaxf(xv.z, 0.f), fmaxf(xv.w, 0.f) };
#pragma unroll
        for (int kk = 0; kk < 4; kk++) {
            const float4* w4 = (const float4*)(Ws + (size_t)(k4 * 4 + kk) * NCLASS);
#pragma unroll
            for (int n = 0; n < 4; n++) {
                float4 w = w4[n];
                acc[n].x = fmaf(xs[kk], w.x, acc[n].x);
                acc[n].y = fmaf(xs[kk], w.y, acc[n].y);
                acc[n].z = fmaf(xs[kk], w.z, acc[n].z);
                acc[n].w = fmaf(xs[kk], w.w, acc[n].w);
            }
        }
    }

    float4* o = (float4*)(out + (size_t)row * NCLASS);
#pragma unroll
    for (int n = 0; n < 4; n++) o[n] = acc[n];
}

// ---------------------------------------------------------------------------
extern "C" void kernel_launch(void* const* d_in, const int* in_sizes, int n_in,
                              void* d_out, int out_size)
{
    const float* x        = (const float*)d_in[0];
    const int*   adj_rows = (const int*)  d_in[1];
    const int*   adj_cols = (const int*)  d_in[2];
    const float* adj_vals = (const float*)d_in[3];
    const float* fc0_w    = (const float*)d_in[4];
    const float* fc0_b    = (const float*)d_in[5];
    const float* conv_w   = (const float*)d_in[6];
    const float* conv_b   = (const float*)d_in[7];
    const float* fc1_w    = (const float*)d_in[8];
    const float* fc1_b    = (const float*)d_in[9];
    float* out = (float*)d_out;

    float *h0p, *xwp, *ap, *bp;
    int *cntp, *exclp, *bsump, *rptrp, *curp;
    int2 *evp;
    cudaGetSymbolAddress((void**)&h0p,  g_h0);
    cudaGetSymbolAddress((void**)&xwp,  g_xw);
    cudaGetSymbolAddress((void**)&ap,   g_bufA);
    cudaGetSymbolAddress((void**)&bp,   g_bufB);
    cudaGetSymbolAddress((void**)&cntp, g_cnt);
    cudaGetSymbolAddress((void**)&exclp,g_excl);
    cudaGetSymbolAddress((void**)&bsump,g_bsum);
    cudaGetSymbolAddress((void**)&rptrp,g_rptr);
    cudaGetSymbolAddress((void**)&curp, g_cursor);
    cudaGetSymbolAddress((void**)&evp,  g_ev);

    const int GEMM_BLOCKS = (NN + 127) / 128;          // 782
    const int EDGE_BLOCKS = (EE + 255) / 256;          // 4688
    const int SCAN_BLOCKS = (NN + 511) / 512;          // 196
    const int SPMM_BLOCKS = (NN + 7) / 8;              // 12500 (8 warps/block)

    // --- build CSR once (reused by all 4 SpMM layers) ---
    k_zero<<<(NN + 255) / 256, 256>>>(cntp, NN);
    k_hist<<<EDGE_BLOCKS, 256>>>(adj_rows, cntp);
    k_scan1<<<SCAN_BLOCKS, 512>>>(cntp, exclp, bsump);
    k_scan2<<<1, 512>>>(bsump, SCAN_BLOCKS);
    k_finish<<<SCAN_BLOCKS, 512>>>(exclp, bsump, rptrp, curp);
    k_fill<<<EDGE_BLOCKS, 256>>>(adj_rows, adj_cols, adj_vals, curp, evp);

    // --- fc0: h0 = x @ fc0_w + fc0_b (pre-ReLU; ReLU applied at consumers) ---
    tile_gemm<NFEAT_K, false, true><<<GEMM_BLOCKS, 256>>>(x, fc0_w, fc0_b, h0p);

    // --- 4 GCNII layers (theta cancels: out = 0.9*A@(relu(li)@W) + 0.1*h0 + b) ---
    float* prev = h0p;
    float* bufs[2] = { ap, bp };
    for (int i = 0; i < 4; i++) {
        float* next = bufs[i & 1];
        tile_gemm<NHID, true, false><<<GEMM_BLOCKS, 256>>>(
            prev, conv_w + (size_t)i * NHID * NHID, nullptr, xwp);
        spmm_pull<<<SPMM_BLOCKS, 256>>>(rptrp, evp, xwp, h0p,
                                        conv_b + (size_t)i * NHID, next);
        prev = next;
    }

    // --- fc1: out = relu(prev) @ fc1_w + fc1_b ---
    fc1_kernel<<<(NN + 255) / 256, 256>>>(prev, fc1_w, fc1_b, out);
}

// round 5
// speedup vs baseline: 3.1582x; 1.1946x over previous
#include <cuda_runtime.h>
#include <cuda_fp16.h>
#include <cstddef>

#define NN      100000
#define EE      1200000
#define NFEAT_K 128
#define NHID    64
#define NCLASS  16

// ---- scratch (__device__ globals; no runtime allocation allowed) ----------
__device__ float  g_h0 [(size_t)NN * NHID];    // h = x@fc0_w + fc0_b (pre-ReLU)
__device__ __half g_xwh[(size_t)NN * NHID];    // relu(prev)@conv_w[i], fp16 gather operand
__device__ float  g_bufA[(size_t)NN * NHID];   // layer outputs (ping)
__device__ float  g_bufB[(size_t)NN * NHID];   // layer outputs (pong)
// CSR (built once per launch; adjacency identical across the 4 layers)
__device__ int    g_cnt   [NN];
__device__ int    g_excl  [NN];
__device__ int    g_bsum  [256];
__device__ int    g_rptr  [NN + 1];
__device__ int    g_cursor[NN];
__device__ int2   g_ev    [EE];                // (col, __float_as_int(0.9*val))

// ---------------------------------------------------------------------------
// Register-tiled GEMM: out = act(in) @ W[K,64] (+ b). Block tile 128x64x64,
// 256 threads, thread tile 8x4. HALF_OUT stores fp16 (SpMM gather operand).
// ---------------------------------------------------------------------------
template<int K, bool RELU_IN, bool ADD_BIAS, bool HALF_OUT>
__global__ __launch_bounds__(256)
void tile_gemm(const float* __restrict__ in, const float* __restrict__ W,
               const float* __restrict__ b, void* __restrict__ outv)
{
    constexpr int BM = 128, BN = 64, BK = 64;
    __shared__ float4 xs4[BM][BK / 4];   // 32KB
    __shared__ float4 ws4[BK][BN / 4];   // 16KB

    const int t    = threadIdx.x;
    const int ng   = t & 15;             // column group (4 cols)
    const int mg   = t >> 4;             // row group (8 rows)
    const int row0 = blockIdx.x * BM;

    float4 acc[8];
#pragma unroll
    for (int r = 0; r < 8; r++) acc[r] = make_float4(0.f, 0.f, 0.f, 0.f);

    for (int kt = 0; kt < K; kt += BK) {
        {
            const float4* Wg = (const float4*)(W + (size_t)kt * BN);
#pragma unroll
            for (int i = t; i < BK * BN / 4; i += 256)
                ws4[i >> 4][i & 15] = __ldg(Wg + i);
        }
#pragma unroll
        for (int i = t; i < BM * BK / 4; i += 256) {
            int r  = i >> 4;
            int k4 = i & 15;
            int row = row0 + r;
            float4 v = make_float4(0.f, 0.f, 0.f, 0.f);
            if (row < NN) v = __ldg((const float4*)(in + (size_t)row * K + kt) + k4);
            if (RELU_IN) {
                v.x = fmaxf(v.x, 0.f); v.y = fmaxf(v.y, 0.f);
                v.z = fmaxf(v.z, 0.f); v.w = fmaxf(v.w, 0.f);
            }
            xs4[r][k4] = v;
        }
        __syncthreads();

#pragma unroll 4
        for (int k4 = 0; k4 < BK / 4; k4++) {
            float4 w0 = ws4[k4 * 4 + 0][ng];
            float4 w1 = ws4[k4 * 4 + 1][ng];
            float4 w2 = ws4[k4 * 4 + 2][ng];
            float4 w3 = ws4[k4 * 4 + 3][ng];
#pragma unroll
            for (int r = 0; r < 8; r++) {
                float4 xv = xs4[mg * 8 + r][k4];
                acc[r].x = fmaf(xv.x, w0.x, acc[r].x);
                acc[r].y = fmaf(xv.x, w0.y, acc[r].y);
                acc[r].z = fmaf(xv.x, w0.z, acc[r].z);
                acc[r].w = fmaf(xv.x, w0.w, acc[r].w);
                acc[r].x = fmaf(xv.y, w1.x, acc[r].x);
                acc[r].y = fmaf(xv.y, w1.y, acc[r].y);
                acc[r].z = fmaf(xv.y, w1.z, acc[r].z);
                acc[r].w = fmaf(xv.y, w1.w, acc[r].w);
                acc[r].x = fmaf(xv.z, w2.x, acc[r].x);
                acc[r].y = fmaf(xv.z, w2.y, acc[r].y);
                acc[r].z = fmaf(xv.z, w2.z, acc[r].z);
                acc[r].w = fmaf(xv.z, w2.w, acc[r].w);
                acc[r].x = fmaf(xv.w, w3.x, acc[r].x);
                acc[r].y = fmaf(xv.w, w3.y, acc[r].y);
                acc[r].z = fmaf(xv.w, w3.z, acc[r].z);
                acc[r].w = fmaf(xv.w, w3.w, acc[r].w);
            }
        }
        __syncthreads();
    }

    float4 bias = make_float4(0.f, 0.f, 0.f, 0.f);
    if (ADD_BIAS) bias = __ldg((const float4*)(b + ng * 4));
#pragma unroll
    for (int r = 0; r < 8; r++) {
        int row = row0 + mg * 8 + r;
        if (row >= NN) break;
        float4 o = acc[r];
        if (ADD_BIAS) { o.x += bias.x; o.y += bias.y; o.z += bias.z; o.w += bias.w; }
        if (HALF_OUT) {
            __half2 h01 = __floats2half2_rn(o.x, o.y);
            __half2 h23 = __floats2half2_rn(o.z, o.w);
            __half2* dst = (__half2*)((__half*)outv + (size_t)row * BN + ng * 4);
            dst[0] = h01; dst[1] = h23;
        } else {
            *((float4*)((float*)outv + (size_t)row * BN + ng * 4)) = o;
        }
    }
}

// ---------------------------------------------------------------------------
// CSR build (adjacency fixed across layers -> build once per launch)
// ---------------------------------------------------------------------------
__global__ void k_hist(const int* __restrict__ rows, int* __restrict__ cnt)
{
    int e = blockIdx.x * 256 + threadIdx.x;
    if (e < EE) atomicAdd(cnt + __ldg(rows + e), 1);
}

__device__ __forceinline__ int block_scan_excl_512(int v, int* total)
{
    int lane = threadIdx.x & 31, warp = threadIdx.x >> 5;
    int x = v;
#pragma unroll
    for (int d = 1; d < 32; d <<= 1) {
        int y = __shfl_up_sync(0xffffffffu, x, d);
        if (lane >= d) x += y;
    }
    __shared__ int wsum[16];
    if (lane == 31) wsum[warp] = x;
    __syncthreads();
    if (warp == 0) {
        int y = (lane < 16) ? wsum[lane] : 0;
#pragma unroll
        for (int d = 1; d < 16; d <<= 1) {
            int z = __shfl_up_sync(0xffffffffu, y, d);
            if (lane >= d) y += z;
        }
        if (lane < 16) wsum[lane] = y;
    }
    __syncthreads();
    int off = (warp > 0) ? wsum[warp - 1] : 0;
    if (total) *total = wsum[15];
    return x + off - v;   // exclusive
}

__global__ __launch_bounds__(512)
void k_scan1(const int* __restrict__ cnt, int* __restrict__ excl, int* __restrict__ bsum)
{
    int i = blockIdx.x * 512 + threadIdx.x;
    int v = (i < NN) ? cnt[i] : 0;
    int total;
    int ex = block_scan_excl_512(v, &total);
    if (i < NN) excl[i] = ex;
    if (threadIdx.x == 0) bsum[blockIdx.x] = total;
}

// Finish: every block redundantly scans the (small) bsum array in smem,
// then adds its offset. Folds the former single-block middle scan in.
__global__ __launch_bounds__(512)
void k_finish(const int* __restrict__ excl, const int* __restrict__ bsum, int nblk,
              int* __restrict__ rptr, int* __restrict__ cursor)
{
    __shared__ int sofs[512];
    int v = (threadIdx.x < nblk) ? __ldg(bsum + threadIdx.x) : 0;
    int ex = block_scan_excl_512(v, nullptr);
    sofs[threadIdx.x] = ex;
    __syncthreads();
    int boff = sofs[blockIdx.x];

    int i = blockIdx.x * 512 + threadIdx.x;
    if (i < NN) {
        int p = excl[i] + boff;
        rptr[i] = p;
        cursor[i] = p;
    }
    if (i == 0) rptr[NN] = EE;
}

__global__ void k_fill(const int* __restrict__ rows, const int* __restrict__ cols,
                       const float* __restrict__ vals,
                       int* __restrict__ cursor, int2* __restrict__ ev)
{
    int e = blockIdx.x * 256 + threadIdx.x;
    if (e >= EE) return;
    int r = __ldg(rows + e);
    int p = atomicAdd(cursor + r, 1);
    ev[p] = make_int2(__ldg(cols + e), __float_as_int(0.9f * __ldg(vals + e)));
}

// ---------------------------------------------------------------------------
// SpMM pull (CSR by destination), fp16 gather, fused GCNII epilogue:
//   out[r,:] = 0.1*h0[r,:] + cb[:] + sum_e 0.9*val_e * xwh[col_e,:]
// One warp per row; lane owns a half2 (2 features). Edge loop unrolled x2
// for MLP on the L2-latency chain. fp32 accumulation. No atomics.
// ---------------------------------------------------------------------------
__global__ __launch_bounds__(256)
void spmm_pull(const int* __restrict__ rptr, const int2* __restrict__ ev,
               const __half2* __restrict__ xwh, const float* __restrict__ h0,
               const float* __restrict__ cb, float* __restrict__ out)
{
    int r    = (blockIdx.x * 256 + threadIdx.x) >> 5;
    int lane = threadIdx.x & 31;
    if (r >= NN) return;

    int start = __ldg(rptr + r);
    int end   = __ldg(rptr + r + 1);

    float2 h = __ldg((const float2*)(h0 + (size_t)r * NHID) + lane);
    float2 c = __ldg((const float2*)cb + lane);
    float2 acc = make_float2(fmaf(0.1f, h.x, c.x), fmaf(0.1f, h.y, c.y));

    int e = start;
    for (; e + 1 < end; e += 2) {
        int2 e0 = __ldg(ev + e);
        int2 e1 = __ldg(ev + e + 1);
        __half2 x0 = __ldg(xwh + (size_t)e0.x * (NHID / 2) + lane);
        __half2 x1 = __ldg(xwh + (size_t)e1.x * (NHID / 2) + lane);
        float v0 = __int_as_float(e0.y);
        float v1 = __int_as_float(e1.y);
        float2 f0 = __half22float2(x0);
        float2 f1 = __half22float2(x1);
        acc.x = fmaf(v0, f0.x, acc.x);
        acc.y = fmaf(v0, f0.y, acc.y);
        acc.x = fmaf(v1, f1.x, acc.x);
        acc.y = fmaf(v1, f1.y, acc.y);
    }
    if (e < end) {
        int2 e0 = __ldg(ev + e);
        __half2 x0 = __ldg(xwh + (size_t)e0.x * (NHID / 2) + lane);
        float v0 = __int_as_float(e0.y);
        float2 f0 = __half22float2(x0);
        acc.x = fmaf(v0, f0.x, acc.x);
        acc.y = fmaf(v0, f0.y, acc.y);
    }

    *((float2*)(out + (size_t)r * NHID) + lane) = acc;
}

// ---------------------------------------------------------------------------
// fc1: out[r,:] = relu(in[r,:]) @ W[64,16] + b. One thread per row.
// ---------------------------------------------------------------------------
__global__ __launch_bounds__(256)
void fc1_kernel(const float* __restrict__ in, const float* __restrict__ W,
                const float* __restrict__ b, float* __restrict__ out)
{
    __shared__ float Ws[NHID * NCLASS];
    __shared__ float bs[NCLASS];
    for (int i = threadIdx.x; i < NHID * NCLASS; i += 256) Ws[i] = W[i];
    if (threadIdx.x < NCLASS) bs[threadIdx.x] = b[threadIdx.x];
    __syncthreads();

    int row = blockIdx.x * 256 + threadIdx.x;
    if (row >= NN) return;

    float4 acc[4];
    const float4* b4 = (const float4*)bs;
#pragma unroll
    for (int n = 0; n < 4; n++) acc[n] = b4[n];

    const float4* inr = (const float4*)(in + (size_t)row * NHID);
#pragma unroll 4
    for (int k4 = 0; k4 < NHID / 4; k4++) {
        float4 xv = __ldg(inr + k4);
        float xs[4] = { fmaxf(xv.x, 0.f), fmaxf(xv.y, 0.f),
                        fmaxf(xv.z, 0.f), fmaxf(xv.w, 0.f) };
#pragma unroll
        for (int kk = 0; kk < 4; kk++) {
            const float4* w4 = (const float4*)(Ws + (size_t)(k4 * 4 + kk) * NCLASS);
#pragma unroll
            for (int n = 0; n < 4; n++) {
                float4 w = w4[n];
                acc[n].x = fmaf(xs[kk], w.x, acc[n].x);
                acc[n].y = fmaf(xs[kk], w.y, acc[n].y);
                acc[n].z = fmaf(xs[kk], w.z, acc[n].z);
                acc[n].w = fmaf(xs[kk], w.w, acc[n].w);
            }
        }
    }

    float4* o = (float4*)(out + (size_t)row * NCLASS);
#pragma unroll
    for (int n = 0; n < 4; n++) o[n] = acc[n];
}

// ---------------------------------------------------------------------------
extern "C" void kernel_launch(void* const* d_in, const int* in_sizes, int n_in,
                              void* d_out, int out_size)
{
    const float* x        = (const float*)d_in[0];
    const int*   adj_rows = (const int*)  d_in[1];
    const int*   adj_cols = (const int*)  d_in[2];
    const float* adj_vals = (const float*)d_in[3];
    const float* fc0_w    = (const float*)d_in[4];
    const float* fc0_b    = (const float*)d_in[5];
    const float* conv_w   = (const float*)d_in[6];
    const float* conv_b   = (const float*)d_in[7];
    const float* fc1_w    = (const float*)d_in[8];
    const float* fc1_b    = (const float*)d_in[9];
    float* out = (float*)d_out;

    float *h0p, *ap, *bp;
    __half *xwhp;
    int *cntp, *exclp, *bsump, *rptrp, *curp;
    int2 *evp;
    cudaGetSymbolAddress((void**)&h0p,  g_h0);
    cudaGetSymbolAddress((void**)&xwhp, g_xwh);
    cudaGetSymbolAddress((void**)&ap,   g_bufA);
    cudaGetSymbolAddress((void**)&bp,   g_bufB);
    cudaGetSymbolAddress((void**)&cntp, g_cnt);
    cudaGetSymbolAddress((void**)&exclp,g_excl);
    cudaGetSymbolAddress((void**)&bsump,g_bsum);
    cudaGetSymbolAddress((void**)&rptrp,g_rptr);
    cudaGetSymbolAddress((void**)&curp, g_cursor);
    cudaGetSymbolAddress((void**)&evp,  g_ev);

    const int GEMM_BLOCKS = (NN + 127) / 128;          // 782
    const int EDGE_BLOCKS = (EE + 255) / 256;          // 4688
    const int SCAN_BLOCKS = (NN + 511) / 512;          // 196
    const int SPMM_BLOCKS = (NN + 7) / 8;              // 12500 (8 warps/block)

    // --- build CSR once (reused by all 4 SpMM layers) ---
    cudaMemsetAsync(cntp, 0, NN * sizeof(int));
    k_hist<<<EDGE_BLOCKS, 256>>>(adj_rows, cntp);
    k_scan1<<<SCAN_BLOCKS, 512>>>(cntp, exclp, bsump);
    k_finish<<<SCAN_BLOCKS, 512>>>(exclp, bsump, SCAN_BLOCKS, rptrp, curp);
    k_fill<<<EDGE_BLOCKS, 256>>>(adj_rows, adj_cols, adj_vals, curp, evp);

    // --- fc0: h0 = x @ fc0_w + fc0_b (pre-ReLU; ReLU applied at consumers) ---
    tile_gemm<NFEAT_K, false, true, false><<<GEMM_BLOCKS, 256>>>(x, fc0_w, fc0_b, h0p);

    // --- 4 GCNII layers (theta cancels: out = 0.9*A@(relu(li)@W) + 0.1*h0 + b) ---
    float* prev = h0p;
    float* bufs[2] = { ap, bp };
    for (int i = 0; i < 4; i++) {
        float* next = bufs[i & 1];
        tile_gemm<NHID, true, false, true><<<GEMM_BLOCKS, 256>>>(
            prev, conv_w + (size_t)i * NHID * NHID, nullptr, xwhp);
        spmm_pull<<<SPMM_BLOCKS, 256>>>(rptrp, evp, (const __half2*)xwhp, h0p,
                                        conv_b + (size_t)i * NHID, next);
        prev = next;
    }

    // --- fc1: out = relu(prev) @ fc1_w + fc1_b ---
    fc1_kernel<<<(NN + 255) / 256, 256>>>(prev, fc1_w, fc1_b, out);
}

// round 6
// speedup vs baseline: 3.2067x; 1.0154x over previous
#include <cuda_runtime.h>
#include <cuda_fp16.h>
#include <cstddef>

#define NN      100000
#define EE      1200000
#define NFEAT_K 128
#define NHID    64
#define NCLASS  16

// ---- scratch (__device__ globals; no runtime allocation allowed) ----------
__device__ float  g_h0 [(size_t)NN * NHID];    // h = x@fc0_w + fc0_b (pre-ReLU)
__device__ __half g_xwh[(size_t)NN * NHID];    // relu(prev)@conv_w[i], fp16 gather operand
__device__ float  g_bufA[(size_t)NN * NHID];   // layer outputs (ping)
__device__ float  g_bufB[(size_t)NN * NHID];   // layer outputs (pong)
// CSR (built once per launch; adjacency identical across the 4 layers)
__device__ int    g_cnt   [NN];
__device__ int    g_excl  [NN];
__device__ int    g_bsum  [256];
__device__ int    g_rptr  [NN + 1];
__device__ int    g_cursor[NN];
__device__ int2   g_ev    [EE];                // (col, __float_as_int(0.9*val))

// ---------------------------------------------------------------------------
// Register-tiled GEMM: out = act(in) @ W[K,64] (+ b). Block tile 128x64x64,
// 256 threads, thread tile 8x4. HALF_OUT stores fp16 (SpMM gather operand).
// ---------------------------------------------------------------------------
template<int K, bool RELU_IN, bool ADD_BIAS, bool HALF_OUT>
__global__ __launch_bounds__(256)
void tile_gemm(const float* __restrict__ in, const float* __restrict__ W,
               const float* __restrict__ b, void* __restrict__ outv)
{
    constexpr int BM = 128, BN = 64, BK = 64;
    __shared__ float4 xs4[BM][BK / 4];   // 32KB
    __shared__ float4 ws4[BK][BN / 4];   // 16KB

    const int t    = threadIdx.x;
    const int ng   = t & 15;             // column group (4 cols)
    const int mg   = t >> 4;             // row group (8 rows)
    const int row0 = blockIdx.x * BM;

    float4 acc[8];
#pragma unroll
    for (int r = 0; r < 8; r++) acc[r] = make_float4(0.f, 0.f, 0.f, 0.f);

    for (int kt = 0; kt < K; kt += BK) {
        {
            const float4* Wg = (const float4*)(W + (size_t)kt * BN);
#pragma unroll
            for (int i = t; i < BK * BN / 4; i += 256)
                ws4[i >> 4][i & 15] = __ldg(Wg + i);
        }
#pragma unroll
        for (int i = t; i < BM * BK / 4; i += 256) {
            int r  = i >> 4;
            int k4 = i & 15;
            int row = row0 + r;
            float4 v = make_float4(0.f, 0.f, 0.f, 0.f);
            if (row < NN) v = __ldg((const float4*)(in + (size_t)row * K + kt) + k4);
            if (RELU_IN) {
                v.x = fmaxf(v.x, 0.f); v.y = fmaxf(v.y, 0.f);
                v.z = fmaxf(v.z, 0.f); v.w = fmaxf(v.w, 0.f);
            }
            xs4[r][k4] = v;
        }
        __syncthreads();

#pragma unroll 4
        for (int k4 = 0; k4 < BK / 4; k4++) {
            float4 w0 = ws4[k4 * 4 + 0][ng];
            float4 w1 = ws4[k4 * 4 + 1][ng];
            float4 w2 = ws4[k4 * 4 + 2][ng];
            float4 w3 = ws4[k4 * 4 + 3][ng];
#pragma unroll
            for (int r = 0; r < 8; r++) {
                float4 xv = xs4[mg * 8 + r][k4];
                acc[r].x = fmaf(xv.x, w0.x, acc[r].x);
                acc[r].y = fmaf(xv.x, w0.y, acc[r].y);
                acc[r].z = fmaf(xv.x, w0.z, acc[r].z);
                acc[r].w = fmaf(xv.x, w0.w, acc[r].w);
                acc[r].x = fmaf(xv.y, w1.x, acc[r].x);
                acc[r].y = fmaf(xv.y, w1.y, acc[r].y);
                acc[r].z = fmaf(xv.y, w1.z, acc[r].z);
                acc[r].w = fmaf(xv.y, w1.w, acc[r].w);
                acc[r].x = fmaf(xv.z, w2.x, acc[r].x);
                acc[r].y = fmaf(xv.z, w2.y, acc[r].y);
                acc[r].z = fmaf(xv.z, w2.z, acc[r].z);
                acc[r].w = fmaf(xv.z, w2.w, acc[r].w);
                acc[r].x = fmaf(xv.w, w3.x, acc[r].x);
                acc[r].y = fmaf(xv.w, w3.y, acc[r].y);
                acc[r].z = fmaf(xv.w, w3.z, acc[r].z);
                acc[r].w = fmaf(xv.w, w3.w, acc[r].w);
            }
        }
        __syncthreads();
    }

    float4 bias = make_float4(0.f, 0.f, 0.f, 0.f);
    if (ADD_BIAS) bias = __ldg((const float4*)(b + ng * 4));
#pragma unroll
    for (int r = 0; r < 8; r++) {
        int row = row0 + mg * 8 + r;
        if (row >= NN) break;
        float4 o = acc[r];
        if (ADD_BIAS) { o.x += bias.x; o.y += bias.y; o.z += bias.z; o.w += bias.w; }
        if (HALF_OUT) {
            __half2 h01 = __floats2half2_rn(o.x, o.y);
            __half2 h23 = __floats2half2_rn(o.z, o.w);
            __half2* dst = (__half2*)((__half*)outv + (size_t)row * BN + ng * 4);
            dst[0] = h01; dst[1] = h23;
        } else {
            *((float4*)((float*)outv + (size_t)row * BN + ng * 4)) = o;
        }
    }
}

// ---------------------------------------------------------------------------
// CSR build (adjacency fixed across layers -> build once per launch).
// hist/fill process 4 edges per thread for MLP on the atomic/scatter chains.
// ---------------------------------------------------------------------------
__global__ void k_hist(const int* __restrict__ rows, int* __restrict__ cnt)
{
    int base = blockIdx.x * 1024 + threadIdx.x;
#pragma unroll
    for (int j = 0; j < 4; j++) {
        int e = base + j * 256;
        if (e < EE) atomicAdd(cnt + __ldg(rows + e), 1);
    }
}

__device__ __forceinline__ int block_scan_excl_512(int v, int* total)
{
    int lane = threadIdx.x & 31, warp = threadIdx.x >> 5;
    int x = v;
#pragma unroll
    for (int d = 1; d < 32; d <<= 1) {
        int y = __shfl_up_sync(0xffffffffu, x, d);
        if (lane >= d) x += y;
    }
    __shared__ int wsum[16];
    if (lane == 31) wsum[warp] = x;
    __syncthreads();
    if (warp == 0) {
        int y = (lane < 16) ? wsum[lane] : 0;
#pragma unroll
        for (int d = 1; d < 16; d <<= 1) {
            int z = __shfl_up_sync(0xffffffffu, y, d);
            if (lane >= d) y += z;
        }
        if (lane < 16) wsum[lane] = y;
    }
    __syncthreads();
    int off = (warp > 0) ? wsum[warp - 1] : 0;
    if (total) *total = wsum[15];
    return x + off - v;   // exclusive
}

__global__ __launch_bounds__(512)
void k_scan1(const int* __restrict__ cnt, int* __restrict__ excl, int* __restrict__ bsum)
{
    int i = blockIdx.x * 512 + threadIdx.x;
    int v = (i < NN) ? cnt[i] : 0;
    int total;
    int ex = block_scan_excl_512(v, &total);
    if (i < NN) excl[i] = ex;
    if (threadIdx.x == 0) bsum[blockIdx.x] = total;
}

// Finish: every block redundantly scans the (small) bsum array in smem,
// then adds its offset (folds the middle single-block scan in).
__global__ __launch_bounds__(512)
void k_finish(const int* __restrict__ excl, const int* __restrict__ bsum, int nblk,
              int* __restrict__ rptr, int* __restrict__ cursor)
{
    __shared__ int sofs[512];
    int v = (threadIdx.x < nblk) ? __ldg(bsum + threadIdx.x) : 0;
    int ex = block_scan_excl_512(v, nullptr);
    sofs[threadIdx.x] = ex;
    __syncthreads();
    int boff = sofs[blockIdx.x];

    int i = blockIdx.x * 512 + threadIdx.x;
    if (i < NN) {
        int p = excl[i] + boff;
        rptr[i] = p;
        cursor[i] = p;
    }
    if (i == 0) rptr[NN] = EE;
}

__global__ void k_fill(const int* __restrict__ rows, const int* __restrict__ cols,
                       const float* __restrict__ vals,
                       int* __restrict__ cursor, int2* __restrict__ ev)
{
    int base = blockIdx.x * 1024 + threadIdx.x;
#pragma unroll
    for (int j = 0; j < 4; j++) {
        int e = base + j * 256;
        if (e < EE) {
            int r = __ldg(rows + e);
            int p = atomicAdd(cursor + r, 1);
            ev[p] = make_int2(__ldg(cols + e), __float_as_int(0.9f * __ldg(vals + e)));
        }
    }
}

// ---------------------------------------------------------------------------
// SpMM pull (CSR by destination), fp16 gather, fused GCNII epilogue:
//   out[r,:] = 0.1*h0[r,:] + cb[:] + sum_e 0.9*val_e * xwh[col_e,:]
// One warp per row; lane owns a half2. Edge loop unrolled x4 (4 independent
// L2 gathers in flight). fp32 accumulation. No atomics.
// ---------------------------------------------------------------------------
__global__ __launch_bounds__(256)
void spmm_pull(const int* __restrict__ rptr, const int2* __restrict__ ev,
               const __half2* __restrict__ xwh, const float* __restrict__ h0,
               const float* __restrict__ cb, float* __restrict__ out)
{
    int r    = (blockIdx.x * 256 + threadIdx.x) >> 5;
    int lane = threadIdx.x & 31;
    if (r >= NN) return;

    int start = __ldg(rptr + r);
    int end   = __ldg(rptr + r + 1);

    float2 h = __ldg((const float2*)(h0 + (size_t)r * NHID) + lane);
    float2 c = __ldg((const float2*)cb + lane);
    float2 acc = make_float2(fmaf(0.1f, h.x, c.x), fmaf(0.1f, h.y, c.y));

    int e = start;
    for (; e + 3 < end; e += 4) {
        int2 e0 = __ldg(ev + e);
        int2 e1 = __ldg(ev + e + 1);
        int2 e2 = __ldg(ev + e + 2);
        int2 e3 = __ldg(ev + e + 3);
        __half2 x0 = __ldg(xwh + (size_t)e0.x * (NHID / 2) + lane);
        __half2 x1 = __ldg(xwh + (size_t)e1.x * (NHID / 2) + lane);
        __half2 x2 = __ldg(xwh + (size_t)e2.x * (NHID / 2) + lane);
        __half2 x3 = __ldg(xwh + (size_t)e3.x * (NHID / 2) + lane);
        float2 f0 = __half22float2(x0);
        float2 f1 = __half22float2(x1);
        float2 f2 = __half22float2(x2);
        float2 f3 = __half22float2(x3);
        float v0 = __int_as_float(e0.y), v1 = __int_as_float(e1.y);
        float v2 = __int_as_float(e2.y), v3 = __int_as_float(e3.y);
        acc.x = fmaf(v0, f0.x, acc.x);  acc.y = fmaf(v0, f0.y, acc.y);
        acc.x = fmaf(v1, f1.x, acc.x);  acc.y = fmaf(v1, f1.y, acc.y);
        acc.x = fmaf(v2, f2.x, acc.x);  acc.y = fmaf(v2, f2.y, acc.y);
        acc.x = fmaf(v3, f3.x, acc.x);  acc.y = fmaf(v3, f3.y, acc.y);
    }
    for (; e < end; e++) {
        int2 e0 = __ldg(ev + e);
        __half2 x0 = __ldg(xwh + (size_t)e0.x * (NHID / 2) + lane);
        float v0 = __int_as_float(e0.y);
        float2 f0 = __half22float2(x0);
        acc.x = fmaf(v0, f0.x, acc.x);
        acc.y = fmaf(v0, f0.y, acc.y);
    }

    *((float2*)(out + (size_t)r * NHID) + lane) = acc;
}

// ---------------------------------------------------------------------------
// fc1: out[r,:] = relu(in[r,:]) @ W[64,16] + b. One thread per row.
// ---------------------------------------------------------------------------
__global__ __launch_bounds__(256)
void fc1_kernel(const float* __restrict__ in, const float* __restrict__ W,
                const float* __restrict__ b, float* __restrict__ out)
{
    __shared__ float Ws[NHID * NCLASS];
    __shared__ float bs[NCLASS];
    for (int i = threadIdx.x; i < NHID * NCLASS; i += 256) Ws[i] = W[i];
    if (threadIdx.x < NCLASS) bs[threadIdx.x] = b[threadIdx.x];
    __syncthreads();

    int row = blockIdx.x * 256 + threadIdx.x;
    if (row >= NN) return;

    float4 acc[4];
    const float4* b4 = (const float4*)bs;
#pragma unroll
    for (int n = 0; n < 4; n++) acc[n] = b4[n];

    const float4* inr = (const float4*)(in + (size_t)row * NHID);
#pragma unroll 4
    for (int k4 = 0; k4 < NHID / 4; k4++) {
        float4 xv = __ldg(inr + k4);
        float xs[4] = { fmaxf(xv.x, 0.f), fmaxf(xv.y, 0.f),
                        fmaxf(xv.z, 0.f), fmaxf(xv.w, 0.f) };
#pragma unroll
        for (int kk = 0; kk < 4; kk++) {
            const float4* w4 = (const float4*)(Ws + (size_t)(k4 * 4 + kk) * NCLASS);
#pragma unroll
            for (int n = 0; n < 4; n++) {
                float4 w = w4[n];
                acc[n].x = fmaf(xs[kk], w.x, acc[n].x);
                acc[n].y = fmaf(xs[kk], w.y, acc[n].y);
                acc[n].z = fmaf(xs[kk], w.z, acc[n].z);
                acc[n].w = fmaf(xs[kk], w.w, acc[n].w);
            }
        }
    }

    float4* o = (float4*)(out + (size_t)row * NCLASS);
#pragma unroll
    for (int n = 0; n < 4; n++) o[n] = acc[n];
}

// ---------------------------------------------------------------------------
extern "C" void kernel_launch(void* const* d_in, const int* in_sizes, int n_in,
                              void* d_out, int out_size)
{
    const float* x        = (const float*)d_in[0];
    const int*   adj_rows = (const int*)  d_in[1];
    const int*   adj_cols = (const int*)  d_in[2];
    const float* adj_vals = (const float*)d_in[3];
    const float* fc0_w    = (const float*)d_in[4];
    const float* fc0_b    = (const float*)d_in[5];
    const float* conv_w   = (const float*)d_in[6];
    const float* conv_b   = (const float*)d_in[7];
    const float* fc1_w    = (const float*)d_in[8];
    const float* fc1_b    = (const float*)d_in[9];
    float* out = (float*)d_out;

    float *h0p, *ap, *bp;
    __half *xwhp;
    int *cntp, *exclp, *bsump, *rptrp, *curp;
    int2 *evp;
    cudaGetSymbolAddress((void**)&h0p,  g_h0);
    cudaGetSymbolAddress((void**)&xwhp, g_xwh);
    cudaGetSymbolAddress((void**)&ap,   g_bufA);
    cudaGetSymbolAddress((void**)&bp,   g_bufB);
    cudaGetSymbolAddress((void**)&cntp, g_cnt);
    cudaGetSymbolAddress((void**)&exclp,g_excl);
    cudaGetSymbolAddress((void**)&bsump,g_bsum);
    cudaGetSymbolAddress((void**)&rptrp,g_rptr);
    cudaGetSymbolAddress((void**)&curp, g_cursor);
    cudaGetSymbolAddress((void**)&evp,  g_ev);

    // One-time stream/event handles (resource init, not work caching — the
    // same launches happen on every call).
    static cudaStream_t s2 = nullptr;
    static cudaEvent_t  evFork = nullptr, evGemm0 = nullptr;
    if (!s2) {
        cudaStreamCreateWithFlags(&s2, cudaStreamNonBlocking);
        cudaEventCreateWithFlags(&evFork,  cudaEventDisableTiming);
        cudaEventCreateWithFlags(&evGemm0, cudaEventDisableTiming);
    }

    const int GEMM_BLOCKS = (NN + 127) / 128;          // 782
    const int E4_BLOCKS   = (EE + 1023) / 1024;        // 1172 (4 edges/thread)
    const int SCAN_BLOCKS = (NN + 511) / 512;          // 196
    const int SPMM_BLOCKS = (NN + 7) / 8;              // 12500 (8 warps/block)

    // ---- fork: dense branch (s2) runs concurrently with CSR build (main) ----
    cudaEventRecord(evFork, 0);
    cudaStreamWaitEvent(s2, evFork, 0);

    // s2: fc0 then layer-0 conv GEMM (independent of CSR build)
    tile_gemm<NFEAT_K, false, true, false><<<GEMM_BLOCKS, 256, 0, s2>>>(
        x, fc0_w, fc0_b, h0p);
    tile_gemm<NHID, true, false, true><<<GEMM_BLOCKS, 256, 0, s2>>>(
        h0p, conv_w, nullptr, xwhp);
    cudaEventRecord(evGemm0, s2);

    // main: CSR build (reused by all 4 SpMM layers)
    cudaMemsetAsync(cntp, 0, NN * sizeof(int));
    k_hist<<<E4_BLOCKS, 256>>>(adj_rows, cntp);
    k_scan1<<<SCAN_BLOCKS, 512>>>(cntp, exclp, bsump);
    k_finish<<<SCAN_BLOCKS, 512>>>(exclp, bsump, SCAN_BLOCKS, rptrp, curp);
    k_fill<<<E4_BLOCKS, 256>>>(adj_rows, adj_cols, adj_vals, curp, evp);

    // join: first SpMM needs CSR (main) + xwh/h0 (s2)
    cudaStreamWaitEvent(0, evGemm0, 0);

    // ---- 4 GCNII layers (theta cancels: out = 0.9*A@(relu(li)@W) + 0.1*h0 + b)
    float* prev = h0p;
    float* bufs[2] = { ap, bp };
    for (int i = 0; i < 4; i++) {
        float* next = bufs[i & 1];
        if (i > 0) {
            tile_gemm<NHID, true, false, true><<<GEMM_BLOCKS, 256>>>(
                prev, conv_w + (size_t)i * NHID * NHID, nullptr, xwhp);
        }
        spmm_pull<<<SPMM_BLOCKS, 256>>>(rptrp, evp, (const __half2*)xwhp, h0p,
                                        conv_b + (size_t)i * NHID, next);
        prev = next;
    }

    // ---- fc1: out = relu(prev) @ fc1_w + fc1_b ----
    fc1_kernel<<<(NN + 255) / 256, 256>>>(prev, fc1_w, fc1_b, out);
}

// round 7
// speedup vs baseline: 3.8335x; 1.1955x over previous
#include <cuda_runtime.h>
#include <cuda_fp16.h>
#include <mma.h>
#include <cstddef>

using namespace nvcuda;

#define NN      100000
#define EE      1200000
#define NFEAT_K 128
#define NHID    64
#define NCLASS  16
#define NN_PAD  100096   // NN rounded up to 128 (wmma stores unguarded per tile)

// ---- scratch (__device__ globals; no runtime allocation allowed) ----------
__device__ float  g_h0 [(size_t)NN * NHID];      // h = x@fc0_w + fc0_b (pre-ReLU)
__device__ __half g_xwh[(size_t)NN_PAD * NHID];  // relu(prev)@conv_w[i], fp16
__device__ float  g_bufA[(size_t)NN * NHID];     // layer outputs (ping)
__device__ float  g_bufB[(size_t)NN * NHID];     // layer outputs (pong)
// CSR (built once per launch; adjacency identical across the 4 layers)
__device__ int    g_cnt   [NN];
__device__ int    g_excl  [NN];
__device__ int    g_bsum  [256];
__device__ int    g_rptr  [NN + 1];
__device__ int    g_cursor[NN];
__device__ int2   g_ev    [EE];                  // (col, __float_as_int(0.9*val))

// ---------------------------------------------------------------------------
// Tensor-core conv GEMM: xwh[r,:] = fp16( relu(in[r,:]) @ W[64,64] )
// Block tile 128x64, K=64 single stage. 8 warps in a 4(M) x 2(N) grid,
// warp tile 32x32 via wmma m16n16k16 (fp16 in, fp32 accum).
// Inputs staged fp32 -> relu -> fp16 into padded smem (ldm=72, LDSM-friendly).
// Output converted in-fragment to fp16 and stored straight to gmem (the SpMM
// gather operand is fp16 anyway) -- no epilogue smem roundtrip.
// ---------------------------------------------------------------------------
__global__ __launch_bounds__(256)
void conv_gemm_wmma(const float* __restrict__ in, const float* __restrict__ W,
                    __half* __restrict__ out)
{
    constexpr int LDA = 72;   // halves (144B rows; padding kills LDSM conflicts)
    __shared__ __half As[128 * LDA];
    __shared__ __half Bs[64 * LDA];

    const int t    = threadIdx.x;
    const int row0 = blockIdx.x * 128;

    // Stage A: 128 rows x 64 cols, float4 loads, relu, convert to half
#pragma unroll
    for (int i = t; i < 128 * 16; i += 256) {
        int r  = i >> 4;
        int c4 = i & 15;
        int row = row0 + r;
        float4 v = make_float4(0.f, 0.f, 0.f, 0.f);
        if (row < NN) v = __ldg((const float4*)(in + (size_t)row * NHID) + c4);
        __half2* dst = (__half2*)(As + r * LDA + c4 * 4);
        dst[0] = __floats2half2_rn(fmaxf(v.x, 0.f), fmaxf(v.y, 0.f));
        dst[1] = __floats2half2_rn(fmaxf(v.z, 0.f), fmaxf(v.w, 0.f));
    }
    // Stage B: W[64][64] fp32 -> half
#pragma unroll
    for (int i = t; i < 64 * 16; i += 256) {
        int r  = i >> 4;
        int c4 = i & 15;
        float4 v = __ldg((const float4*)(W + (size_t)r * 64) + c4);
        __half2* dst = (__half2*)(Bs + r * LDA + c4 * 4);
        dst[0] = __floats2half2_rn(v.x, v.y);
        dst[1] = __floats2half2_rn(v.z, v.w);
    }
    __syncthreads();

    const int wid = t >> 5;
    const int wm  = wid & 3;    // 4 warps along M (32 rows each)
    const int wn  = wid >> 2;   // 2 warps along N (32 cols each)

    wmma::fragment<wmma::accumulator, 16, 16, 16, float> c[2][2];
#pragma unroll
    for (int i = 0; i < 2; i++)
#pragma unroll
        for (int j = 0; j < 2; j++) wmma::fill_fragment(c[i][j], 0.f);

#pragma unroll
    for (int k = 0; k < 64; k += 16) {
        wmma::fragment<wmma::matrix_a, 16, 16, 16, __half, wmma::row_major> a0, a1;
        wmma::fragment<wmma::matrix_b, 16, 16, 16, __half, wmma::row_major> b0, b1;
        wmma::load_matrix_sync(a0, As + (wm * 32 +  0) * LDA + k, LDA);
        wmma::load_matrix_sync(a1, As + (wm * 32 + 16) * LDA + k, LDA);
        wmma::load_matrix_sync(b0, Bs + k * LDA + wn * 32 +  0, LDA);
        wmma::load_matrix_sync(b1, Bs + k * LDA + wn * 32 + 16, LDA);
        wmma::mma_sync(c[0][0], a0, b0, c[0][0]);
        wmma::mma_sync(c[0][1], a0, b1, c[0][1]);
        wmma::mma_sync(c[1][0], a1, b0, c[1][0]);
        wmma::mma_sync(c[1][1], a1, b1, c[1][1]);
    }

    // Convert accumulators to fp16 in-fragment and store (out padded to NN_PAD)
#pragma unroll
    for (int i = 0; i < 2; i++)
#pragma unroll
        for (int j = 0; j < 2; j++) {
            wmma::fragment<wmma::accumulator, 16, 16, 16, __half> hc;
#pragma unroll
            for (int e = 0; e < hc.num_elements; e++)
                hc.x[e] = __float2half(c[i][j].x[e]);
            __half* dst = out + (size_t)(row0 + wm * 32 + i * 16) * 64
                              + wn * 32 + j * 16;
            wmma::store_matrix_sync(dst, hc, 64, wmma::mem_row_major);
        }
}

// ---------------------------------------------------------------------------
// fp32 register-tiled GEMM (fc0): out = in @ W[K,64] + b. Block 128x64x64.
// ---------------------------------------------------------------------------
template<int K>
__global__ __launch_bounds__(256)
void tile_gemm_f32(const float* __restrict__ in, const float* __restrict__ W,
                   const float* __restrict__ b, float* __restrict__ out)
{
    constexpr int BM = 128, BN = 64, BK = 64;
    __shared__ float4 xs4[BM][BK / 4];
    __shared__ float4 ws4[BK][BN / 4];

    const int t    = threadIdx.x;
    const int ng   = t & 15;
    const int mg   = t >> 4;
    const int row0 = blockIdx.x * BM;

    float4 acc[8];
#pragma unroll
    for (int r = 0; r < 8; r++) acc[r] = make_float4(0.f, 0.f, 0.f, 0.f);

    for (int kt = 0; kt < K; kt += BK) {
        {
            const float4* Wg = (const float4*)(W + (size_t)kt * BN);
#pragma unroll
            for (int i = t; i < BK * BN / 4; i += 256)
                ws4[i >> 4][i & 15] = __ldg(Wg + i);
        }
#pragma unroll
        for (int i = t; i < BM * BK / 4; i += 256) {
            int r  = i >> 4;
            int k4 = i & 15;
            int row = row0 + r;
            float4 v = make_float4(0.f, 0.f, 0.f, 0.f);
            if (row < NN) v = __ldg((const float4*)(in + (size_t)row * K + kt) + k4);
            xs4[r][k4] = v;
        }
        __syncthreads();

#pragma unroll 4
        for (int k4 = 0; k4 < BK / 4; k4++) {
            float4 w0 = ws4[k4 * 4 + 0][ng];
            float4 w1 = ws4[k4 * 4 + 1][ng];
            float4 w2 = ws4[k4 * 4 + 2][ng];
            float4 w3 = ws4[k4 * 4 + 3][ng];
#pragma unroll
            for (int r = 0; r < 8; r++) {
                float4 xv = xs4[mg * 8 + r][k4];
                acc[r].x = fmaf(xv.x, w0.x, acc[r].x);
                acc[r].y = fmaf(xv.x, w0.y, acc[r].y);
                acc[r].z = fmaf(xv.x, w0.z, acc[r].z);
                acc[r].w = fmaf(xv.x, w0.w, acc[r].w);
                acc[r].x = fmaf(xv.y, w1.x, acc[r].x);
                acc[r].y = fmaf(xv.y, w1.y, acc[r].y);
                acc[r].z = fmaf(xv.y, w1.z, acc[r].z);
                acc[r].w = fmaf(xv.y, w1.w, acc[r].w);
                acc[r].x = fmaf(xv.z, w2.x, acc[r].x);
                acc[r].y = fmaf(xv.z, w2.y, acc[r].y);
                acc[r].z = fmaf(xv.z, w2.z, acc[r].z);
                acc[r].w = fmaf(xv.z, w2.w, acc[r].w);
                acc[r].x = fmaf(xv.w, w3.x, acc[r].x);
                acc[r].y = fmaf(xv.w, w3.y, acc[r].y);
                acc[r].z = fmaf(xv.w, w3.z, acc[r].z);
                acc[r].w = fmaf(xv.w, w3.w, acc[r].w);
            }
        }
        __syncthreads();
    }

    float4 bias = __ldg((const float4*)(b + ng * 4));
#pragma unroll
    for (int r = 0; r < 8; r++) {
        int row = row0 + mg * 8 + r;
        if (row >= NN) break;
        float4 o = acc[r];
        o.x += bias.x; o.y += bias.y; o.z += bias.z; o.w += bias.w;
        *((float4*)(out + (size_t)row * 64 + ng * 4)) = o;
    }
}

// ---------------------------------------------------------------------------
// CSR build (adjacency fixed across layers -> build once per launch)
// ---------------------------------------------------------------------------
__global__ void k_hist(const int* __restrict__ rows, int* __restrict__ cnt)
{
    int base = blockIdx.x * 1024 + threadIdx.x;
#pragma unroll
    for (int j = 0; j < 4; j++) {
        int e = base + j * 256;
        if (e < EE) atomicAdd(cnt + __ldg(rows + e), 1);
    }
}

__device__ __forceinline__ int block_scan_excl_512(int v, int* total)
{
    int lane = threadIdx.x & 31, warp = threadIdx.x >> 5;
    int x = v;
#pragma unroll
    for (int d = 1; d < 32; d <<= 1) {
        int y = __shfl_up_sync(0xffffffffu, x, d);
        if (lane >= d) x += y;
    }
    __shared__ int wsum[16];
    if (lane == 31) wsum[warp] = x;
    __syncthreads();
    if (warp == 0) {
        int y = (lane < 16) ? wsum[lane] : 0;
#pragma unroll
        for (int d = 1; d < 16; d <<= 1) {
            int z = __shfl_up_sync(0xffffffffu, y, d);
            if (lane >= d) y += z;
        }
        if (lane < 16) wsum[lane] = y;
    }
    __syncthreads();
    int off = (warp > 0) ? wsum[warp - 1] : 0;
    if (total) *total = wsum[15];
    return x + off - v;   // exclusive
}

__global__ __launch_bounds__(512)
void k_scan1(const int* __restrict__ cnt, int* __restrict__ excl, int* __restrict__ bsum)
{
    int i = blockIdx.x * 512 + threadIdx.x;
    int v = (i < NN) ? cnt[i] : 0;
    int total;
    int ex = block_scan_excl_512(v, &total);
    if (i < NN) excl[i] = ex;
    if (threadIdx.x == 0) bsum[blockIdx.x] = total;
}

__global__ __launch_bounds__(512)
void k_finish(const int* __restrict__ excl, const int* __restrict__ bsum, int nblk,
              int* __restrict__ rptr, int* __restrict__ cursor)
{
    __shared__ int sofs[512];
    int v = (threadIdx.x < nblk) ? __ldg(bsum + threadIdx.x) : 0;
    int ex = block_scan_excl_512(v, nullptr);
    sofs[threadIdx.x] = ex;
    __syncthreads();
    int boff = sofs[blockIdx.x];

    int i = blockIdx.x * 512 + threadIdx.x;
    if (i < NN) {
        int p = excl[i] + boff;
        rptr[i] = p;
        cursor[i] = p;
    }
    if (i == 0) rptr[NN] = EE;
}

__global__ void k_fill(const int* __restrict__ rows, const int* __restrict__ cols,
                       const float* __restrict__ vals,
                       int* __restrict__ cursor, int2* __restrict__ ev)
{
    int base = blockIdx.x * 1024 + threadIdx.x;
#pragma unroll
    for (int j = 0; j < 4; j++) {
        int e = base + j * 256;
        if (e < EE) {
            int r = __ldg(rows + e);
            int p = atomicAdd(cursor + r, 1);
            ev[p] = make_int2(__ldg(cols + e), __float_as_int(0.9f * __ldg(vals + e)));
        }
    }
}

// ---------------------------------------------------------------------------
// SpMM pull (CSR by destination), fp16 gather, fused GCNII epilogue:
//   out[r,:] = 0.1*h0[r,:] + cb[:] + sum_e 0.9*val_e * xwh[col_e,:]
// One warp per row; lane owns a half2. Edge loop unrolled x4. No atomics.
// ---------------------------------------------------------------------------
__global__ __launch_bounds__(256)
void spmm_pull(const int* __restrict__ rptr, const int2* __restrict__ ev,
               const __half2* __restrict__ xwh, const float* __restrict__ h0,
               const float* __restrict__ cb, float* __restrict__ out)
{
    int r    = (blockIdx.x * 256 + threadIdx.x) >> 5;
    int lane = threadIdx.x & 31;
    if (r >= NN) return;

    int start = __ldg(rptr + r);
    int end   = __ldg(rptr + r + 1);

    float2 h = __ldg((const float2*)(h0 + (size_t)r * NHID) + lane);
    float2 c = __ldg((const float2*)cb + lane);
    float2 acc = make_float2(fmaf(0.1f, h.x, c.x), fmaf(0.1f, h.y, c.y));

    int e = start;
    for (; e + 3 < end; e += 4) {
        int2 e0 = __ldg(ev + e);
        int2 e1 = __ldg(ev + e + 1);
        int2 e2 = __ldg(ev + e + 2);
        int2 e3 = __ldg(ev + e + 3);
        __half2 x0 = __ldg(xwh + (size_t)e0.x * (NHID / 2) + lane);
        __half2 x1 = __ldg(xwh + (size_t)e1.x * (NHID / 2) + lane);
        __half2 x2 = __ldg(xwh + (size_t)e2.x * (NHID / 2) + lane);
        __half2 x3 = __ldg(xwh + (size_t)e3.x * (NHID / 2) + lane);
        float2 f0 = __half22float2(x0);
        float2 f1 = __half22float2(x1);
        float2 f2 = __half22float2(x2);
        float2 f3 = __half22float2(x3);
        float v0 = __int_as_float(e0.y), v1 = __int_as_float(e1.y);
        float v2 = __int_as_float(e2.y), v3 = __int_as_float(e3.y);
        acc.x = fmaf(v0, f0.x, acc.x);  acc.y = fmaf(v0, f0.y, acc.y);
        acc.x = fmaf(v1, f1.x, acc.x);  acc.y = fmaf(v1, f1.y, acc.y);
        acc.x = fmaf(v2, f2.x, acc.x);  acc.y = fmaf(v2, f2.y, acc.y);
        acc.x = fmaf(v3, f3.x, acc.x);  acc.y = fmaf(v3, f3.y, acc.y);
    }
    for (; e < end; e++) {
        int2 e0 = __ldg(ev + e);
        __half2 x0 = __ldg(xwh + (size_t)e0.x * (NHID / 2) + lane);
        float v0 = __int_as_float(e0.y);
        float2 f0 = __half22float2(x0);
        acc.x = fmaf(v0, f0.x, acc.x);
        acc.y = fmaf(v0, f0.y, acc.y);
    }

    *((float2*)(out + (size_t)r * NHID) + lane) = acc;
}

// ---------------------------------------------------------------------------
// fc1: out[r,:] = relu(in[r,:]) @ W[64,16] + b. One thread per row.
// ---------------------------------------------------------------------------
__global__ __launch_bounds__(256)
void fc1_kernel(const float* __restrict__ in, const float* __restrict__ W,
                const float* __restrict__ b, float* __restrict__ out)
{
    __shared__ float Ws[NHID * NCLASS];
    __shared__ float bs[NCLASS];
    for (int i = threadIdx.x; i < NHID * NCLASS; i += 256) Ws[i] = W[i];
    if (threadIdx.x < NCLASS) bs[threadIdx.x] = b[threadIdx.x];
    __syncthreads();

    int row = blockIdx.x * 256 + threadIdx.x;
    if (row >= NN) return;

    float4 acc[4];
    const float4* b4 = (const float4*)bs;
#pragma unroll
    for (int n = 0; n < 4; n++) acc[n] = b4[n];

    const float4* inr = (const float4*)(in + (size_t)row * NHID);
#pragma unroll 4
    for (int k4 = 0; k4 < NHID / 4; k4++) {
        float4 xv = __ldg(inr + k4);
        float xs[4] = { fmaxf(xv.x, 0.f), fmaxf(xv.y, 0.f),
                        fmaxf(xv.z, 0.f), fmaxf(xv.w, 0.f) };
#pragma unroll
        for (int kk = 0; kk < 4; kk++) {
            const float4* w4 = (const float4*)(Ws + (size_t)(k4 * 4 + kk) * NCLASS);
#pragma unroll
            for (int n = 0; n < 4; n++) {
                float4 w = w4[n];
                acc[n].x = fmaf(xs[kk], w.x, acc[n].x);
                acc[n].y = fmaf(xs[kk], w.y, acc[n].y);
                acc[n].z = fmaf(xs[kk], w.z, acc[n].z);
                acc[n].w = fmaf(xs[kk], w.w, acc[n].w);
            }
        }
    }

    float4* o = (float4*)(out + (size_t)row * NCLASS);
#pragma unroll
    for (int n = 0; n < 4; n++) o[n] = acc[n];
}

// ---------------------------------------------------------------------------
extern "C" void kernel_launch(void* const* d_in, const int* in_sizes, int n_in,
                              void* d_out, int out_size)
{
    const float* x        = (const float*)d_in[0];
    const int*   adj_rows = (const int*)  d_in[1];
    const int*   adj_cols = (const int*)  d_in[2];
    const float* adj_vals = (const float*)d_in[3];
    const float* fc0_w    = (const float*)d_in[4];
    const float* fc0_b    = (const float*)d_in[5];
    const float* conv_w   = (const float*)d_in[6];
    const float* conv_b   = (const float*)d_in[7];
    const float* fc1_w    = (const float*)d_in[8];
    const float* fc1_b    = (const float*)d_in[9];
    float* out = (float*)d_out;

    float *h0p, *ap, *bp;
    __half *xwhp;
    int *cntp, *exclp, *bsump, *rptrp, *curp;
    int2 *evp;
    cudaGetSymbolAddress((void**)&h0p,  g_h0);
    cudaGetSymbolAddress((void**)&xwhp, g_xwh);
    cudaGetSymbolAddress((void**)&ap,   g_bufA);
    cudaGetSymbolAddress((void**)&bp,   g_bufB);
    cudaGetSymbolAddress((void**)&cntp, g_cnt);
    cudaGetSymbolAddress((void**)&exclp,g_excl);
    cudaGetSymbolAddress((void**)&bsump,g_bsum);
    cudaGetSymbolAddress((void**)&rptrp,g_rptr);
    cudaGetSymbolAddress((void**)&curp, g_cursor);
    cudaGetSymbolAddress((void**)&evp,  g_ev);

    // One-time stream/event handles (resource init, not work caching).
    static cudaStream_t s2 = nullptr;
    static cudaEvent_t  evFork = nullptr, evGemm0 = nullptr;
    if (!s2) {
        cudaStreamCreateWithFlags(&s2, cudaStreamNonBlocking);
        cudaEventCreateWithFlags(&evFork,  cudaEventDisableTiming);
        cudaEventCreateWithFlags(&evGemm0, cudaEventDisableTiming);
    }

    const int GEMM_BLOCKS = (NN + 127) / 128;          // 782
    const int E4_BLOCKS   = (EE + 1023) / 1024;        // 1172
    const int SCAN_BLOCKS = (NN + 511) / 512;          // 196
    const int SPMM_BLOCKS = (NN + 7) / 8;              // 12500

    // ---- fork: dense branch (s2) concurrent with CSR build (main) ----
    cudaEventRecord(evFork, 0);
    cudaStreamWaitEvent(s2, evFork, 0);

    // s2: fc0 (fp32) then layer-0 conv GEMM (tensor cores)
    tile_gemm_f32<NFEAT_K><<<GEMM_BLOCKS, 256, 0, s2>>>(x, fc0_w, fc0_b, h0p);
    conv_gemm_wmma<<<GEMM_BLOCKS, 256, 0, s2>>>(h0p, conv_w, xwhp);
    cudaEventRecord(evGemm0, s2);

    // main: CSR build (reused by all 4 SpMM layers)
    cudaMemsetAsync(cntp, 0, NN * sizeof(int));
    k_hist<<<E4_BLOCKS, 256>>>(adj_rows, cntp);
    k_scan1<<<SCAN_BLOCKS, 512>>>(cntp, exclp, bsump);
    k_finish<<<SCAN_BLOCKS, 512>>>(exclp, bsump, SCAN_BLOCKS, rptrp, curp);
    k_fill<<<E4_BLOCKS, 256>>>(adj_rows, adj_cols, adj_vals, curp, evp);

    // join: first SpMM needs CSR (main) + xwh/h0 (s2)
    cudaStreamWaitEvent(0, evGemm0, 0);

    // ---- 4 GCNII layers (theta cancels: out = 0.9*A@(relu(li)@W) + 0.1*h0 + b)
    float* prev = h0p;
    float* bufs[2] = { ap, bp };
    for (int i = 0; i < 4; i++) {
        float* next = bufs[i & 1];
        if (i > 0) {
            conv_gemm_wmma<<<GEMM_BLOCKS, 256>>>(
                prev, conv_w + (size_t)i * NHID * NHID, xwhp);
        }
        spmm_pull<<<SPMM_BLOCKS, 256>>>(rptrp, evp, (const __half2*)xwhp, h0p,
                                        conv_b + (size_t)i * NHID, next);
        prev = next;
    }

    // ---- fc1: out = relu(prev) @ fc1_w + fc1_b ----
    fc1_kernel<<<(NN + 255) / 256, 256>>>(prev, fc1_w, fc1_b, out);
}